// round 1
// baseline (speedup 1.0000x reference)
#include <cuda_runtime.h>
#include <math.h>

#define NN 8192
#define DD 256

// ---------------- scratch (device globals; no allocations allowed) ----------
__device__ float g_H0[NN * DD];            // x @ W (pre-relu, pre-agg)
__device__ float g_ACC[NN * DD];           // segment-sum accumulator
__device__ float g_Wt[DD * DD];            // W transposed (row-major [N,K] for NT gemm)
__device__ float g_SQ[NN];                 // row squared norms of h
__device__ float g_DIST[(size_t)NN * NN];  // pairwise distances (256 MB)
__device__ float g_S[NN];                  // per-row distance-space threshold
__device__ float g_DF[NN];                 // diagonal membership flag (0/1)

// ---------------- reduction helpers ----------------------------------------
__device__ __forceinline__ float blockSum(float v, float* red) {
    int lane = threadIdx.x & 31, wid = threadIdx.x >> 5;
#pragma unroll
    for (int o = 16; o; o >>= 1) v += __shfl_xor_sync(0xffffffffu, v, o);
    if (lane == 0) red[wid] = v;
    __syncthreads();
    if (threadIdx.x < 32) {
        float x = (lane < 8) ? red[lane] : 0.f;
#pragma unroll
        for (int o = 4; o; o >>= 1) x += __shfl_xor_sync(0xffffffffu, x, o);
        if (lane == 0) red[0] = x;
    }
    __syncthreads();
    float r = red[0];
    __syncthreads();
    return r;
}

__device__ __forceinline__ float blockMax(float v, float* red) {
    int lane = threadIdx.x & 31, wid = threadIdx.x >> 5;
#pragma unroll
    for (int o = 16; o; o >>= 1) v = fmaxf(v, __shfl_xor_sync(0xffffffffu, v, o));
    if (lane == 0) red[wid] = v;
    __syncthreads();
    if (threadIdx.x < 32) {
        float x = (lane < 8) ? red[lane] : -3.4e38f;
#pragma unroll
        for (int o = 4; o; o >>= 1) x = fmaxf(x, __shfl_xor_sync(0xffffffffu, x, o));
        if (lane == 0) red[0] = x;
    }
    __syncthreads();
    float r = red[0];
    __syncthreads();
    return r;
}

// ---------------- small kernels ---------------------------------------------
__global__ void transpose_w(const float* __restrict__ W, float* __restrict__ Wt) {
    int idx = blockIdx.x * 256 + threadIdx.x;   // 65536 elements
    int n = idx >> 8, k = idx & 255;
    Wt[idx] = W[k * DD + n];                    // Wt[n][k] = W[k][n]
}

__global__ void zero_acc(float* __restrict__ p, int n) {
    int i = blockIdx.x * blockDim.x + threadIdx.x;
    if (i < n) p[i] = 0.f;
}

__global__ void __launch_bounds__(256)
scatter_edges(const float* __restrict__ H0, const int* __restrict__ edges, int nE,
              float* __restrict__ ACC) {
    int gid = blockIdx.x * 256 + threadIdx.x;
    int e = gid >> 6;
    if (e >= nE) return;
    int c = (gid & 63) << 2;
    int sN = edges[e];
    int dN = edges[nE + e];
    const float4 v = *(const float4*)(H0 + (size_t)sN * DD + c);
    float* p = ACC + (size_t)dN * DD + c;
    atomicAdd(p + 0, v.x); atomicAdd(p + 1, v.y);
    atomicAdd(p + 2, v.z); atomicAdd(p + 3, v.w);
}

__global__ void __launch_bounds__(256)
relu_sq(const float* __restrict__ H0, const float* __restrict__ ACC,
        float* __restrict__ Hout, float* __restrict__ SQ) {
    __shared__ float red[8];
    int r = blockIdx.x, c = threadIdx.x;
    float v = H0[(size_t)r * DD + c] + ACC[(size_t)r * DD + c];
    v = fmaxf(v, 0.f);
    Hout[(size_t)r * DD + c] = v;
    float ss = blockSum(v * v, red);
    if (c == 0) SQ[r] = ss;
}

// ---------------- NT SGEMM: C[M,N] = A[M,K] * B[N,K]^T ----------------------
// 128x128 tile, BK=8, 256 threads, 8x8 per thread.
// EPI==1: C = sqrt(max(sq[i]+sq[j]-2*acc, 0))  (pairwise euclidean distance)
template <int EPI>
__global__ void __launch_bounds__(256)
gemm_nt_128(const float* __restrict__ A, const float* __restrict__ B,
            float* __restrict__ C, int M, int N, int K,
            const float* __restrict__ sq) {
    __shared__ float As[8][132];
    __shared__ float Bs[8][132];
    const int bi = blockIdx.y * 128;
    const int bj = blockIdx.x * 128;
    const int t = threadIdx.x;
    const int tx = t & 15;
    const int ty = t >> 4;
    const int lr = t >> 1;          // 0..127
    const int lc = (t & 1) * 4;     // 0 or 4

    float acc[8][8];
#pragma unroll
    for (int i = 0; i < 8; i++)
#pragma unroll
        for (int j = 0; j < 8; j++) acc[i][j] = 0.f;

    const float* Ag = A + (size_t)(bi + lr) * K + lc;
    const float* Bg = B + (size_t)(bj + lr) * K + lc;

    for (int k0 = 0; k0 < K; k0 += 8) {
        float4 av = *(const float4*)(Ag + k0);
        float4 bv = *(const float4*)(Bg + k0);
        As[lc + 0][lr] = av.x; As[lc + 1][lr] = av.y;
        As[lc + 2][lr] = av.z; As[lc + 3][lr] = av.w;
        Bs[lc + 0][lr] = bv.x; Bs[lc + 1][lr] = bv.y;
        Bs[lc + 2][lr] = bv.z; Bs[lc + 3][lr] = bv.w;
        __syncthreads();
#pragma unroll
        for (int kk = 0; kk < 8; kk++) {
            float ar[8], br[8];
            *(float4*)(ar)     = *(const float4*)(&As[kk][ty * 8]);
            *(float4*)(ar + 4) = *(const float4*)(&As[kk][ty * 8 + 4]);
            *(float4*)(br)     = *(const float4*)(&Bs[kk][tx * 8]);
            *(float4*)(br + 4) = *(const float4*)(&Bs[kk][tx * 8 + 4]);
#pragma unroll
            for (int i = 0; i < 8; i++)
#pragma unroll
                for (int j = 0; j < 8; j++) acc[i][j] = fmaf(ar[i], br[j], acc[i][j]);
        }
        __syncthreads();
    }

    if (EPI == 0) {
#pragma unroll
        for (int i = 0; i < 8; i++) {
            size_t row = (size_t)(bi + ty * 8 + i) * N + bj + tx * 8;
            float4 v0 = make_float4(acc[i][0], acc[i][1], acc[i][2], acc[i][3]);
            float4 v1 = make_float4(acc[i][4], acc[i][5], acc[i][6], acc[i][7]);
            *(float4*)(C + row)     = v0;
            *(float4*)(C + row + 4) = v1;
        }
    } else {
        float si[8], sj[8];
#pragma unroll
        for (int i = 0; i < 8; i++) si[i] = sq[bi + ty * 8 + i];
#pragma unroll
        for (int j = 0; j < 8; j++) sj[j] = sq[bj + tx * 8 + j];
#pragma unroll
        for (int i = 0; i < 8; i++) {
            float tmp[8];
#pragma unroll
            for (int j = 0; j < 8; j++) {
                float d2 = (si[i] + sj[j]) - 2.f * acc[i][j];
                tmp[j] = sqrtf(fmaxf(d2, 0.f));
            }
            size_t row = (size_t)(bi + ty * 8 + i) * N + bj + tx * 8;
            *(float4*)(C + row)     = make_float4(tmp[0], tmp[1], tmp[2], tmp[3]);
            *(float4*)(C + row + 4) = make_float4(tmp[4], tmp[5], tmp[6], tmp[7]);
        }
    }
}

// ---------------- per-row LayerNorm stats + entmax tau root-find ------------
// probs = -dist. zn = gamma*(probs - mean)/(std+eps) + beta, diag set to -1e-6.
// entmax support: p_j > 0  <=>  zn_j/2 > T  where T is unique root of
//   f(T) = sum_j max(zn_j/2 - T, 0)^2 - 1  (convex, decreasing; T in [max-1, max]).
// Store distance-space threshold s: zn > 2T <=> dist < s (since gamma>0).
__global__ void __launch_bounds__(256)
rowsolve(const float* __restrict__ DIST, const float* __restrict__ gamma_p,
         const float* __restrict__ beta_p, float* __restrict__ Sthr,
         float* __restrict__ DF) {
    __shared__ float sv[NN];
    __shared__ float red[8];
    const int r = blockIdx.x;
    const int t = threadIdx.x;
    const float* drow = DIST + (size_t)r * NN;

    // pass 1: load row + sum of dist
    float s = 0.f;
    for (int j = t; j < NN; j += 256) {
        float d = drow[j];
        sv[j] = d;
        s += d;
    }
    __syncthreads();
    float sumd = blockSum(s, red);
    float mean = -sumd * (1.0f / NN);   // mean of probs = -dist

    // pass 2: centered variance (unbiased, ddof=1)
    float v2 = 0.f;
    for (int j = t; j < NN; j += 256) {
        float e = (-sv[j]) - mean;
        v2 += e * e;
    }
    float var = blockSum(v2, red) * (1.0f / (NN - 1));
    float stdv = sqrtf(var);
    float gamma = gamma_p[0], beta = beta_p[0];
    float scale = gamma / (stdv + 1e-6f);
    float a = -scale;                    // zn = a*dist + b
    float b = beta - scale * mean;

    // pass 3: u = zn/2 (diag replaced), rowmax
    float mx = -3.4e38f;
    for (int j = t; j < NN; j += 256) {
        float zn = (j == r) ? -1e-6f : fmaf(a, sv[j], b);
        float u = 0.5f * zn;
        sv[j] = u;
        mx = fmaxf(mx, u);
    }
    __syncthreads();
    mx = blockMax(mx, red);

    // safeguarded Newton on f(T) = sum max(u-T,0)^2 - 1, bracket [mx-1, mx]
    float lo = mx - 1.f, hi = mx, T = lo;
    for (int it = 0; it < 26; it++) {
        float f = 0.f, g = 0.f;
        for (int j = t; j < NN; j += 256) {
            float w = sv[j] - T;
            if (w > 0.f) { f += w * w; g += w; }
        }
        f = blockSum(f, red);
        g = blockSum(g, red);
        f -= 1.f;
        if (f > 0.f) lo = T; else hi = T;
        float Tn = T + f / (2.f * g);    // Newton (f' = -2g)
        if (!(Tn > lo && Tn < hi)) Tn = 0.5f * (lo + hi);
        T = Tn;
    }
    T = 0.5f * (lo + hi);

    if (t == 0) {
        float tzn = 2.f * T;             // threshold in zn-space
        Sthr[r] = (tzn - b) / a;         // a < 0: zn > tzn  <=>  dist < s
        DF[r] = (-1e-6f > tzn) ? 1.f : 0.f;
    }
}

// ---------------- res[i][j] = dist[i][j] < max(s_i, s_j); logprobs ----------
__global__ void __launch_bounds__(256)
finalize(const float* __restrict__ DIST, const float* __restrict__ Sthr,
         const float* __restrict__ DF, float* __restrict__ resOut,
         float* __restrict__ logp) {
    __shared__ float red[8];
    const int i = blockIdx.x;
    const int t = threadIdx.x;
    const float si = Sthr[i];
    const float dfi = DF[i];
    const float* drow = DIST + (size_t)i * NN;
    float* orow = resOut + (size_t)i * NN;
    float cnt = 0.f;
    for (int j = t; j < NN; j += 256) {
        float d = drow[j];
        float sj = Sthr[j];
        float rb = (d < fmaxf(si, sj)) ? 1.f : 0.f;
        if (j == i) rb = dfi;
        orow[j] = rb;
        cnt += rb;
    }
    cnt = blockSum(cnt, red);
    if (t == 0) logp[i] = cnt;
}

// ---------------- launch ------------------------------------------------------
extern "C" void kernel_launch(void* const* d_in, const int* in_sizes, int n_in,
                              void* d_out, int out_size) {
    const float* x     = (const float*)d_in[0];   // [8192, 256]
    const float* W     = (const float*)d_in[1];   // [256, 256]
    const float* gamma = (const float*)d_in[2];   // [1]
    const float* beta  = (const float*)d_in[3];   // [1]
    const int*   edges = (const int*)d_in[4];     // [2, nE]
    int nE = in_sizes[4] / 2;

    float* out    = (float*)d_out;
    float* Hout   = out;                                   // [N*D]
    float* resOut = out + (size_t)NN * DD;                 // [N*N]
    float* logp   = resOut + (size_t)NN * NN;              // [N]

    void *pH0, *pACC, *pWt, *pSQ, *pDIST, *pS, *pDF;
    cudaGetSymbolAddress(&pH0, g_H0);
    cudaGetSymbolAddress(&pACC, g_ACC);
    cudaGetSymbolAddress(&pWt, g_Wt);
    cudaGetSymbolAddress(&pSQ, g_SQ);
    cudaGetSymbolAddress(&pDIST, g_DIST);
    cudaGetSymbolAddress(&pS, g_S);
    cudaGetSymbolAddress(&pDF, g_DF);

    // 1) Wt = W^T
    transpose_w<<<256, 256>>>(W, (float*)pWt);

    // 2) H0 = x @ W   (NT gemm with B = W^T)
    dim3 g1(DD / 128, NN / 128);
    gemm_nt_128<0><<<g1, 256>>>(x, (const float*)pWt, (float*)pH0,
                                NN, DD, DD, nullptr);

    // 3) ACC = 0
    zero_acc<<<(NN * DD + 255) / 256, 256>>>((float*)pACC, NN * DD);

    // 4) ACC[dst] += H0[src] for each edge
    int sgrid = (nE * 64 + 255) / 256;
    scatter_edges<<<sgrid, 256>>>((const float*)pH0, edges, nE, (float*)pACC);

    // 5) h = relu(H0 + ACC) -> output region; SQ = rowwise |h|^2
    relu_sq<<<NN, 256>>>((const float*)pH0, (const float*)pACC, Hout, (float*)pSQ);

    // 6) DIST = pairwise euclidean distances of h
    dim3 g2(NN / 128, NN / 128);
    gemm_nt_128<1><<<g2, 256>>>(Hout, Hout, (float*)pDIST,
                                NN, NN, DD, (const float*)pSQ);

    // 7) per-row layernorm stats + entmax tau -> distance thresholds
    rowsolve<<<NN, 256>>>((const float*)pDIST, gamma, beta,
                          (float*)pS, (float*)pDF);

    // 8) res + logprobs
    finalize<<<NN, 256>>>((const float*)pDIST, (const float*)pS,
                          (const float*)pDF, resOut, logp);
}